// round 6
// baseline (speedup 1.0000x reference)
#include <cuda_runtime.h>
#include <cstdint>

#define QNL 6

struct cpx { float x, y; };
__device__ __forceinline__ cpx cmul(cpx a, cpx b){ return cpx{a.x*b.x - a.y*b.y, a.x*b.y + a.y*b.x}; }
__device__ __forceinline__ cpx cadd(cpx a, cpx b){ return cpx{a.x + b.x, a.y + b.y}; }

__device__ __forceinline__ float tanh_approx(float x){
    float y;
    asm("tanh.approx.f32 %0, %1;" : "=f"(y) : "f"(x));
    return y;
}

// Persistent fused kernel, one wave. Warp 0 of each block computes the 29 model
// coefficients once (exact closed form of both 2-qubit circuits), publishes to
// shared; every thread then pulls them into REGISTERS and streams the batch.
//
// sC[]:
// [0]      K (constant incl. b2[1]-b2[0] and both circuits' identity terms)
// [1..8]   circuit-1 coeffs {cb, sb, ca, ca*cb, ca*sb, sa, sa*cb, sa*sb}
// [9..16]  circuit-2 coeffs, same order
// [17..28] angle affine maps: 4 rows of (w_x0, w_x1, bias) for a1,b1,a2,b2
__global__ __launch_bounds__(256, 6) void hybrid_fused(
    const float4* __restrict__ xin, float4* __restrict__ out, int nf4,
    const float* __restrict__ qw1, const float* __restrict__ qw2,
    const float* __restrict__ W1,  const float* __restrict__ b1,
    const float* __restrict__ W2,  const float* __restrict__ b2)
{
    __shared__ float sC[32];
    __shared__ cpx U[2][4][4];
    __shared__ cpx M[2][2][4][4];
    __shared__ float qs[24], qc[24];
    __shared__ float sW2[8];
    __shared__ float sKb2;
    __shared__ float Kpart[2];

    if (threadIdx.x < 32){
        int t = threadIdx.x;
        int c = t >> 4;          // circuit
        int e = t & 15;          // matrix entry
        int I = e >> 2, J = e & 3;

        // parallel parameter fetch: one round trip for everything
        if (t < 24){
            float th = (t < 12) ? qw1[t] : qw2[t - 12];
            float s, cc;
            __sincosf(th * 0.5f, &s, &cc);
            qs[t] = s; qc[t] = cc;
        }
        if (t < 12) sC[17 + t] = ((t % 3) == 2) ? b1[t / 3] : W1[(t / 3) * 2 + (t % 3)];
        if (t >= 24) sW2[t - 24] = W2[t - 24];
        if (t == 23) sKb2 = b2[1] - b2[0];

        U[c][I][J] = cpx{ (I == J) ? 1.0f : 0.0f, 0.0f };
        __syncwarp();

        // CNOT(q0->q1) permutes rows 2<->3; fold into which T-row we compute.
        int S  = (I < 2) ? I : (5 - I);
        int iS = S >> 1, jS = S & 1;

        for (int l = 0; l < QNL; l++){
            float c0 = qc[c*12 + 2*l],     s0 = qs[c*12 + 2*l];
            float c1 = qc[c*12 + 2*l + 1], s1 = qs[c*12 + 2*l + 1];
            cpx T = cpx{0.f, 0.f};
            #pragma unroll
            for (int K = 0; K < 4; K++){
                int kS = K >> 1, lS = K & 1;
                cpx r0 = (iS == kS) ? cpx{c0, 0.f} : cpx{0.f, -s0};
                cpx r1 = (jS == lS) ? cpx{c1, 0.f} : cpx{0.f, -s1};
                T = cadd(T, cmul(cmul(r0, r1), U[c][K][J]));
            }
            __syncwarp();
            U[c][I][J] = T;
            __syncwarp();
        }

        // M_m = U^dag D_m U, D0 = diag(1,1,-1,-1), D1 = diag(1,-1,1,-1)
        cpx m0 = cpx{0.f,0.f}, m1 = cpx{0.f,0.f};
        #pragma unroll
        for (int K = 0; K < 4; K++){
            cpx a = U[c][K][I];
            cpx b = U[c][K][J];
            cpx tK = cmul(cpx{a.x, -a.y}, b);
            float d0 = (K < 2)  ?  1.f : -1.f;
            float d1 = (K & 1)  ? -1.f :  1.f;
            m0.x += d0*tK.x; m0.y += d0*tK.y;
            m1.x += d1*tK.x; m1.y += d1*tK.y;
        }
        M[c][0][I][J] = m0;
        M[c][1][I][J] = m1;
        __syncwarp();

        if (e < 9){
            int alpha = e / 3, beta = e % 3;  // 0=I, 1=Z(cos), 2=Y(sin)
            float C0 = 0.f, C1 = 0.f;
            #pragma unroll
            for (int ra = 0; ra < 2; ra++){
                int ia = ra;
                int ka = (alpha == 2) ? 1 - ra : ra;
                cpx va = (alpha == 0) ? cpx{1.f, 0.f}
                       : (alpha == 1) ? cpx{ra ? -1.f : 1.f, 0.f}
                                      : cpx{0.f, ra ? 1.f : -1.f};
                #pragma unroll
                for (int rb = 0; rb < 2; rb++){
                    int ib = rb;
                    int kb = (beta == 2) ? 1 - rb : rb;
                    cpx vb = (beta == 0) ? cpx{1.f, 0.f}
                           : (beta == 1) ? cpx{rb ? -1.f : 1.f, 0.f}
                                         : cpx{0.f, rb ? 1.f : -1.f};
                    cpx v = cmul(va, vb);
                    cpx e0 = M[c][0][2*ia + ib][2*ka + kb];
                    cpx e1 = M[c][1][2*ia + ib][2*ka + kb];
                    C0 += v.x*e0.x - v.y*e0.y;
                    C1 += v.x*e1.x - v.y*e1.y;
                }
            }
            float w0 = sW2[4 + 2*c + 0] - sW2[2*c + 0];
            float w1 = sW2[4 + 2*c + 1] - sW2[2*c + 1];
            float g = 0.25f * (w0*C0 + w1*C1);
            if (e == 0) Kpart[c] = g;
            else        sC[8*c + e] = g;
        }
        __syncwarp();
        if (t == 0) sC[0] = sKb2 + Kpart[0] + Kpart[1];
    }
    __syncthreads();

    // ---- pull coefficients into registers (one LDS burst, loop-invariant) ----
    float C[29];
    #pragma unroll
    for (int k = 0; k < 29; k++) C[k] = sC[k];

    // ---- streaming phase: one float4 (2 batch elements) per iteration ----
    const int stride = gridDim.x * blockDim.x;
    for (int i = blockIdx.x * blockDim.x + threadIdx.x; i < nf4; i += stride){
        float4 v = __ldg(&xin[i]);
        float res[4];
        #pragma unroll
        for (int h = 0; h < 2; h++){
            float x0 = h ? v.z : v.x;
            float x1 = h ? v.w : v.y;
            float a1 = fmaf(C[17], x0, fmaf(C[18], x1, C[19]));
            float b1v= fmaf(C[20], x0, fmaf(C[21], x1, C[22]));
            float a2 = fmaf(C[23], x0, fmaf(C[24], x1, C[25]));
            float b2v= fmaf(C[26], x0, fmaf(C[27], x1, C[28]));
            float sa1, ca1, sb1, cb1, sa2, ca2, sb2, cb2;
            __sincosf(a1,  &sa1, &ca1);
            __sincosf(b1v, &sb1, &cb1);
            __sincosf(a2,  &sa2, &ca2);
            __sincosf(b2v, &sb2, &cb2);

            float q1 = fmaf(C[1], cb1, fmaf(C[2],  sb1, C[0]));
            float p1 = ca1 * fmaf(C[4],  cb1, fmaf(C[5],  sb1, C[3]));
            float p2 = sa1 * fmaf(C[7],  cb1, fmaf(C[8],  sb1, C[6]));
            float q2 = fmaf(C[9], cb2, C[10] * sb2);
            float p3 = ca2 * fmaf(C[12], cb2, fmaf(C[13], sb2, C[11]));
            float p4 = sa2 * fmaf(C[15], cb2, fmaf(C[16], sb2, C[14]));

            float d = (q1 + p1) + (p2 + q2) + (p3 + p4);

            // softmax over 2 logits, d = l1 - l0:
            // p0 = 0.5 - 0.5*tanh(d/2), p1 = 0.5 + 0.5*tanh(d/2)
            float th = tanh_approx(0.5f * d);
            res[2*h]     = fmaf(-0.5f, th, 0.5f);
            res[2*h + 1] = fmaf( 0.5f, th, 0.5f);
        }
        out[i] = make_float4(res[0], res[1], res[2], res[3]);
    }
}

extern "C" void kernel_launch(void* const* d_in, const int* in_sizes, int n_in,
                              void* d_out, int out_size){
    const float* x   = (const float*)d_in[0];
    const float* W1  = (const float*)d_in[1];
    const float* b1  = (const float*)d_in[2];
    const float* qw1 = (const float*)d_in[3];
    const float* qw2 = (const float*)d_in[4];
    const float* W2  = (const float*)d_in[5];
    const float* b2  = (const float*)d_in[6];

    int nf4  = in_sizes[0] / 4;       // one float4 = 2 batch elements
    int grid = 148 * 6;               // one full wave at 40 regs / 256 threads
    hybrid_fused<<<grid, 256>>>((const float4*)x, (float4*)d_out, nf4,
                                qw1, qw2, W1, b1, W2, b2);
}

// round 8
// speedup vs baseline: 1.0176x; 1.0176x over previous
#include <cuda_runtime.h>
#include <cstdint>

#define QNL 6

struct cpx { float x, y; };
__device__ __forceinline__ cpx cmul(cpx a, cpx b){ return cpx{a.x*b.x - a.y*b.y, a.x*b.y + a.y*b.x}; }
__device__ __forceinline__ cpx cadd(cpx a, cpx b){ return cpx{a.x + b.x, a.y + b.y}; }

__device__ __forceinline__ float tanh_approx(float x){
    float y;
    asm("tanh.approx.f32 %0, %1;" : "=f"(y) : "f"(x));
    return y;
}

// Persistent fused kernel, one wave. Warp 0 computes the 29 model coefficients
// once (exact closed form of both 2-qubit circuits) into a PACKED float4 layout
// in shared; all threads hoist them into registers and stream the batch.
//
// Packed layout sP[32] (float4-aligned):
//  [0..3]   T0 = (K', C1', C2', C3')      combine coeffs, pre-scaled by 0.5
//  [4..7]   T1 = (C4'..C7')
//  [8..11]  T2 = (C8'..C11')
//  [12..15] T3 = (C12'..C15')
//  [16]     T4 = C16'          [17..19] pad
//  [20..23] A0 = angle-map m17..m20
//  [24..27] A1 = m21..m24
//  [28..31] A2 = m25..m28
__global__ __launch_bounds__(256, 7) void hybrid_fused(
    const float4* __restrict__ xin, float4* __restrict__ out, int nf4,
    const float* __restrict__ qw1, const float* __restrict__ qw2,
    const float* __restrict__ W1,  const float* __restrict__ b1,
    const float* __restrict__ W2,  const float* __restrict__ b2)
{
    __shared__ __align__(16) float sP[32];
    __shared__ cpx U[2][4][4];
    __shared__ cpx M[2][2][4][4];
    __shared__ float qs[24], qc[24];
    __shared__ float sW2[8];
    __shared__ float sKb2;
    __shared__ float Kpart[2];

    if (threadIdx.x < 32){
        int t = threadIdx.x;
        int c = t >> 4;          // circuit
        int e = t & 15;          // matrix entry
        int I = e >> 2, J = e & 3;

        // parallel parameter fetch: one round trip for everything
        if (t < 24){
            float th = (t < 12) ? qw1[t] : qw2[t - 12];
            float s, cc;
            __sincosf(th * 0.5f, &s, &cc);
            qs[t] = s; qc[t] = cc;
        }
        if (t < 12) sP[20 + t] = ((t % 3) == 2) ? b1[t / 3] : W1[(t / 3) * 2 + (t % 3)];
        if (t >= 24) sW2[t - 24] = W2[t - 24];
        if (t == 23) sKb2 = b2[1] - b2[0];
        if (t >= 17 && t <= 19) sP[t] = 0.0f;   // pad

        U[c][I][J] = cpx{ (I == J) ? 1.0f : 0.0f, 0.0f };
        __syncwarp();

        // CNOT(q0->q1) permutes rows 2<->3; fold into which T-row we compute.
        int S  = (I < 2) ? I : (5 - I);
        int iS = S >> 1, jS = S & 1;

        for (int l = 0; l < QNL; l++){
            float c0 = qc[c*12 + 2*l],     s0 = qs[c*12 + 2*l];
            float c1 = qc[c*12 + 2*l + 1], s1 = qs[c*12 + 2*l + 1];
            cpx T = cpx{0.f, 0.f};
            #pragma unroll
            for (int K = 0; K < 4; K++){
                int kS = K >> 1, lS = K & 1;
                cpx r0 = (iS == kS) ? cpx{c0, 0.f} : cpx{0.f, -s0};
                cpx r1 = (jS == lS) ? cpx{c1, 0.f} : cpx{0.f, -s1};
                T = cadd(T, cmul(cmul(r0, r1), U[c][K][J]));
            }
            __syncwarp();
            U[c][I][J] = T;
            __syncwarp();
        }

        // M_m = U^dag D_m U, D0 = diag(1,1,-1,-1), D1 = diag(1,-1,1,-1)
        cpx m0 = cpx{0.f,0.f}, m1 = cpx{0.f,0.f};
        #pragma unroll
        for (int K = 0; K < 4; K++){
            cpx a = U[c][K][I];
            cpx b = U[c][K][J];
            cpx tK = cmul(cpx{a.x, -a.y}, b);
            float d0 = (K < 2)  ?  1.f : -1.f;
            float d1 = (K & 1)  ? -1.f :  1.f;
            m0.x += d0*tK.x; m0.y += d0*tK.y;
            m1.x += d1*tK.x; m1.y += d1*tK.y;
        }
        M[c][0][I][J] = m0;
        M[c][1][I][J] = m1;
        __syncwarp();

        if (e < 9){
            int alpha = e / 3, beta = e % 3;  // 0=I, 1=Z(cos), 2=Y(sin)
            float C0 = 0.f, C1 = 0.f;
            #pragma unroll
            for (int ra = 0; ra < 2; ra++){
                int ia = ra;
                int ka = (alpha == 2) ? 1 - ra : ra;
                cpx va = (alpha == 0) ? cpx{1.f, 0.f}
                       : (alpha == 1) ? cpx{ra ? -1.f : 1.f, 0.f}
                                      : cpx{0.f, ra ? 1.f : -1.f};
                #pragma unroll
                for (int rb = 0; rb < 2; rb++){
                    int ib = rb;
                    int kb = (beta == 2) ? 1 - rb : rb;
                    cpx vb = (beta == 0) ? cpx{1.f, 0.f}
                           : (beta == 1) ? cpx{rb ? -1.f : 1.f, 0.f}
                                         : cpx{0.f, rb ? 1.f : -1.f};
                    cpx v = cmul(va, vb);
                    cpx e0 = M[c][0][2*ia + ib][2*ka + kb];
                    cpx e1 = M[c][1][2*ia + ib][2*ka + kb];
                    C0 += v.x*e0.x - v.y*e0.y;
                    C1 += v.x*e1.x - v.y*e1.y;
                }
            }
            float w0 = sW2[4 + 2*c + 0] - sW2[2*c + 0];
            float w1 = sW2[4 + 2*c + 1] - sW2[2*c + 1];
            // 0.5 tanh-scale folded in: overall 0.5 * 0.25 = 0.125
            float g = 0.125f * (w0*C0 + w1*C1);
            if (e == 0) Kpart[c] = g;
            else        sP[8*c + e] = g;     // c=0 -> 1..8, c=1 -> 9..16
        }
        __syncwarp();
        if (t == 0) sP[0] = 0.5f * sKb2 + Kpart[0] + Kpart[1];
    }
    __syncthreads();

    const float4* sV = (const float4*)sP;

    // ---- hoist coefficients into registers: 8 LDS.128-class loads, once ----
    const float4 T0 = sV[0], T1 = sV[1], T2 = sV[2], T3 = sV[3];
    const float  T4 = sP[16];
    const float4 A0 = sV[5], A1 = sV[6], A2 = sV[7];

    // ---- streaming phase: one float4 (2 batch elements) per iteration ----
    const int stride = gridDim.x * blockDim.x;
    for (int i = blockIdx.x * blockDim.x + threadIdx.x; i < nf4; i += stride){
        float4 v = __ldg(&xin[i]);

        float res[4];
        #pragma unroll
        for (int h = 0; h < 2; h++){
            float x0 = h ? v.z : v.x;
            float x1 = h ? v.w : v.y;
            float a1 = fmaf(A0.x, x0, fmaf(A0.y, x1, A0.z));
            float b1v= fmaf(A0.w, x0, fmaf(A1.x, x1, A1.y));
            float a2 = fmaf(A1.z, x0, fmaf(A1.w, x1, A2.x));
            float b2v= fmaf(A2.y, x0, fmaf(A2.z, x1, A2.w));
            float sa1, ca1, sb1, cb1, sa2, ca2, sb2, cb2;
            __sincosf(a1,  &sa1, &ca1);
            __sincosf(b1v, &sb1, &cb1);
            __sincosf(a2,  &sa2, &ca2);
            __sincosf(b2v, &sb2, &cb2);

            float q1 = fmaf(T0.y, cb1, fmaf(T0.z, sb1, T0.x));
            float p1 = ca1 * fmaf(T1.x, cb1, fmaf(T1.y, sb1, T0.w));
            float p2 = sa1 * fmaf(T1.w, cb1, fmaf(T2.x, sb1, T1.z));
            float q2 = fmaf(T2.y, cb2, T2.z * sb2);
            float p3 = ca2 * fmaf(T3.x, cb2, fmaf(T3.y, sb2, T2.w));
            float p4 = sa2 * fmaf(T3.w, cb2, fmaf(T4,   sb2, T3.z));

            float d = (q1 + p1) + (p2 + q2) + (p3 + p4);

            // softmax over 2 logits (0.5 scale pre-folded into coeffs):
            // p0 = 0.5 - 0.5*tanh(d), p1 = 0.5 + 0.5*tanh(d)
            float th = tanh_approx(d);
            res[2*h]     = fmaf(-0.5f, th, 0.5f);
            res[2*h + 1] = fmaf( 0.5f, th, 0.5f);
        }
        out[i] = make_float4(res[0], res[1], res[2], res[3]);
    }
}

extern "C" void kernel_launch(void* const* d_in, const int* in_sizes, int n_in,
                              void* d_out, int out_size){
    const float* x   = (const float*)d_in[0];
    const float* W1  = (const float*)d_in[1];
    const float* b1  = (const float*)d_in[2];
    const float* qw1 = (const float*)d_in[3];
    const float* qw2 = (const float*)d_in[4];
    const float* W2  = (const float*)d_in[5];
    const float* b2  = (const float*)d_in[6];

    int nf4  = in_sizes[0] / 4;       // one float4 = 2 batch elements
    int grid = 148 * 7;               // one full wave at 36 regs / 256 threads
    hybrid_fused<<<grid, 256>>>((const float4*)x, (float4*)d_out, nf4,
                                qw1, qw2, W1, b1, W2, b2);
}